// round 16
// baseline (speedup 1.0000x reference)
#include <cuda_runtime.h>
#include <cuda_fp16.h>
#include <math.h>
#include <stdint.h>

// ---------------- problem constants ----------------
#define TT 2048
#define HH 1024
#define EE 8
#define FF 3584
#define TOPK 2
#define NPAIR (TT * TOPK)
#define BK 64               // K halfs per chunk (=128B per row)
#define NS 3                // pipeline stages
#define ROWB 144            // smem row stride bytes (128B data + 16B pad)
#define ASTG (128 * ROWB)   // 18432 B  (A tile: 128 rows)
#define BSTG (256 * ROWB)   // 36864 B  (B tile: 256 rows)
#define STG  (ASTG + BSTG)  // 55296 B per stage
#define SMEM_DYN (NS * STG) // 165888 B ; 1 CTA/SM
#define MAXTILES 40
#define EPS 132             // epilogue smem row stride (floats)

// ---------------- device scratch (static; no allocation) ----------------
__device__ int    g_topk_idx[TT][TOPK];
__device__ float  g_topk_w[TT][TOPK];
__device__ int    g_counts[EE];
__device__ int    g_offsets[EE];
__device__ int    g_pair_token[NPAIR];
__device__ float  g_pair_w[NPAIR];
__device__ int    g_slot_of[NPAIR];
__device__ int    g_ntiles;
__device__ int    g_tile_e[MAXTILES];
__device__ int    g_tile_row0[MAXTILES];
__device__ __half g_xs[(size_t)TT * HH];
__device__ __half g_act[(size_t)NPAIR * FF];
__device__ __half g_w1h[(size_t)EE * FF * HH];
__device__ __half g_w3h[(size_t)EE * FF * HH];
__device__ __half g_w2h[(size_t)EE * HH * FF];
__device__ float  g_y[(size_t)NPAIR * HH];

// ---------------- helpers ----------------
__device__ __forceinline__ uint32_t smem_u32(const void* p) {
    uint32_t a;
    asm("{ .reg .u64 t; cvta.to.shared.u64 t, %1; cvt.u32.u64 %0, t; }" : "=r"(a) : "l"(p));
    return a;
}
#define CP16(dst_u32, src_ptr) \
    asm volatile("cp.async.cg.shared.global [%0], [%1], 16;" :: "r"(dst_u32), "l"(src_ptr) : "memory")
#define CP_COMMIT() asm volatile("cp.async.commit_group;" ::: "memory")
#define CP_WAIT(n)  asm volatile("cp.async.wait_group %0;" :: "n"(n) : "memory")
#define LDMX4(r0, r1, r2, r3, addr) \
    asm volatile("ldmatrix.sync.aligned.m8n8.x4.shared.b16 {%0,%1,%2,%3}, [%4];" \
                 : "=r"(r0), "=r"(r1), "=r"(r2), "=r"(r3) : "r"(addr))

__device__ __forceinline__ unsigned h2pack(float lo, float hi) {
    __half2 h = __floats2half2_rn(lo, hi);
    return *(unsigned*)&h;
}
__device__ __forceinline__ void mmaf16(float* c, const unsigned* a, unsigned b0, unsigned b1) {
    asm volatile(
        "mma.sync.aligned.m16n8k16.row.col.f32.f16.f16.f32 "
        "{%0,%1,%2,%3}, {%4,%5,%6,%7}, {%8,%9}, {%0,%1,%2,%3};"
        : "+f"(c[0]), "+f"(c[1]), "+f"(c[2]), "+f"(c[3])
        : "r"(a[0]), "r"(a[1]), "r"(a[2]), "r"(a[3]), "r"(b0), "r"(b1));
}

// ---------------- small kernels ----------------
__global__ void conv_x_kernel(const float* __restrict__ x) {
    int i = blockIdx.x * blockDim.x + threadIdx.x;
    if (i < TT * HH) g_xs[i] = __float2half_rn(x[i]);
}
#define N8_13 (EE * FF * HH / 8)
#define N8_2  (EE * HH * FF / 8)
__global__ void conv_w_all_kernel(const float* __restrict__ w1,
                                  const float* __restrict__ w3,
                                  const float* __restrict__ w2) {
    int i = blockIdx.x * blockDim.x + threadIdx.x;
    const float* src;
    __half* dst;
    int j = i;
    if (j < N8_13)                { src = w1; dst = g_w1h; }
    else if ((j -= N8_13) < N8_13){ src = w3; dst = g_w3h; }
    else if ((j -= N8_13) < N8_2) { src = w2; dst = g_w2h; }
    else return;
    const float4* s = (const float4*)src + 2 * (size_t)j;
    float4 a = s[0], b = s[1];
    uint4 o;
    o.x = h2pack(a.x, a.y);
    o.y = h2pack(a.z, a.w);
    o.z = h2pack(b.x, b.y);
    o.w = h2pack(b.z, b.w);
    ((uint4*)dst)[j] = o;
}
__global__ void router_kernel(const float* __restrict__ x, const float* __restrict__ gw) {
    int warp = (blockIdx.x * blockDim.x + threadIdx.x) >> 5;
    int lane = threadIdx.x & 31;
    if (warp >= TT) return;
    const float* xr = x + (size_t)warp * HH;
    float logit[EE];
#pragma unroll
    for (int e = 0; e < EE; e++) {
        const float* g = gw + (size_t)e * HH;
        float s = 0.0f;
        for (int i = lane; i < HH; i += 32) s += xr[i] * g[i];
#pragma unroll
        for (int o = 16; o > 0; o >>= 1) s += __shfl_xor_sync(0xffffffffu, s, o);
        logit[e] = s;
    }
    if (lane == 0) {
        int i0 = 0;
#pragma unroll
        for (int e = 1; e < EE; e++) if (logit[e] > logit[i0]) i0 = e;
        int i1 = (i0 == 0) ? 1 : 0;
#pragma unroll
        for (int e = 0; e < EE; e++) {
            if (e == i0) continue;
            if (logit[e] > logit[i1]) i1 = e;
        }
        float d = logit[i1] - logit[i0];
        float z = expf(d);
        float w0 = 1.0f / (1.0f + z);
        g_topk_idx[warp][0] = i0;
        g_topk_idx[warp][1] = i1;
        g_topk_w[warp][0] = w0;
        g_topk_w[warp][1] = z * w0;
    }
}
__global__ void build_kernel() {
    __shared__ int s_cnt[EE];
    __shared__ int s_cur[EE];
    int tid = threadIdx.x;
    if (tid < EE) s_cnt[tid] = 0;
    __syncthreads();
    for (int p = tid; p < NPAIR; p += blockDim.x)
        atomicAdd(&s_cnt[g_topk_idx[p >> 1][p & 1]], 1);
    __syncthreads();
    if (tid == 0) {
        int off = 0, nt = 0;
        for (int e = 0; e < EE; e++) {
            g_offsets[e] = off;
            g_counts[e]  = s_cnt[e];
            s_cur[e]     = off;
            for (int r0 = 0; r0 < s_cnt[e]; r0 += 128) {
                g_tile_e[nt]    = e;
                g_tile_row0[nt] = r0;
                nt++;
            }
            off += s_cnt[e];
        }
        g_ntiles = nt;
    }
    __syncthreads();
    for (int p = tid; p < NPAIR; p += blockDim.x) {
        int t = p >> 1, k = p & 1;
        int e = g_topk_idx[t][k];
        int slot = atomicAdd(&s_cur[e], 1);
        g_pair_token[slot] = t;
        g_pair_w[slot]     = g_topk_w[t][k];
        g_slot_of[p]       = slot;
    }
}
__global__ void combine_kernel(float* __restrict__ out) {
    int i = blockIdx.x * blockDim.x + threadIdx.x;
    if (i >= TT * HH / 4) return;
    int t = i >> 8;
    int c = (i & 255) << 2;
    int s0 = g_slot_of[2 * t];
    int s1 = g_slot_of[2 * t + 1];
    float4 a = *(const float4*)(g_y + (size_t)s0 * HH + c);
    float4 b = *(const float4*)(g_y + (size_t)s1 * HH + c);
    *(float4*)(out + (size_t)t * HH + c) =
        make_float4(a.x + b.x, a.y + b.y, a.z + b.z, a.w + b.w);
}

// ======================= GEMM1: act = silu(x@w1^T) * (x@w3^T) =======================
// CTA: 128 token-rows x 128 f-cols. B tile = 128 w1-rows + 128 w3-rows (256 rows).
// Warps: half = wid>>2 (0=g/w1, 1=u/w3); within half 2x2 of 64x64 warp tiles.
__global__ __launch_bounds__(256, 1)
void gemm1_kernel() {
    extern __shared__ char dsm[];
    __shared__ int s_tok[128];

    int ti = blockIdx.y;
    if (ti >= g_ntiles) return;
    int e    = g_tile_e[ti];
    int row0 = g_tile_row0[ti];
    int n_e  = g_counts[e];
    int f0   = blockIdx.x * 128;
    int base = g_offsets[e];
    int tid  = threadIdx.x;

    if (tid < 128) {
        int r = row0 + tid;
        s_tok[tid] = (r < n_e) ? g_pair_token[base + r] : 0;
    }
    __syncthreads();

    // cp.async: A 4x16B + B 8x16B per thread per chunk
    const char* srcA[4];
    const char* srcB[8];
    int dofA[4], dofB[8];
#pragma unroll
    for (int i = 0; i < 4; i++) {
        int idx = tid + 256 * i;
        int row = idx >> 3, c = idx & 7;
        srcA[i] = (const char*)(g_xs + (size_t)s_tok[row] * HH) + c * 16;
        dofA[i] = row * ROWB + c * 16;
    }
#pragma unroll
    for (int i = 0; i < 8; i++) {
        int idx = tid + 256 * i;
        int row = idx >> 3, c = idx & 7;
        const __half* wb = (row < 128)
            ? g_w1h + ((size_t)e * FF + f0 + row) * HH
            : g_w3h + ((size_t)e * FF + f0 + row - 128) * HH;
        srcB[i] = (const char*)wb + c * 16;
        dofB[i] = ASTG + row * ROWB + c * 16;
    }
    uint32_t sb0 = smem_u32(dsm);
    auto issue = [&](int s) {
        uint32_t sg = sb0 + s * STG;
#pragma unroll
        for (int i = 0; i < 4; i++) { CP16(sg + dofA[i], srcA[i]); srcA[i] += 128; }
#pragma unroll
        for (int i = 0; i < 8; i++) { CP16(sg + dofB[i], srcB[i]); srcB[i] += 128; }
        CP_COMMIT();
    };
    issue(0);
    issue(1);

    int wid = tid >> 5, lane = tid & 31;
    int half = wid >> 2;              // 0 = g(w1), 1 = u(w3)
    int wrow = wid & 1;               // M block (64)
    int wcol = (wid >> 1) & 1;        // N block (64) within the 128 f-cols
    int r4 = lane >> 2, qk = lane & 3;
    int lane15 = lane & 15, laneHi = lane >> 4;
    int lane7 = lane & 7, half16 = (lane >> 3) & 1;

    uint32_t aOff[4];
#pragma unroll
    for (int mt = 0; mt < 4; mt++)
        aOff[mt] = (wrow * 64 + mt * 16 + lane15) * ROWB + laneHi * 16;
    uint32_t bOff[4];
#pragma unroll
    for (int pr = 0; pr < 4; pr++) {
        int ntsel = 2 * pr + (lane >> 4);
        bOff[pr] = ASTG + (half * 128 + wcol * 64 + ntsel * 8 + lane7) * ROWB + half16 * 16;
    }

    float acc[4][8][4];
#pragma unroll
    for (int mt = 0; mt < 4; mt++)
#pragma unroll
        for (int nt = 0; nt < 8; nt++)
#pragma unroll
            for (int i = 0; i < 4; i++) acc[mt][nt][i] = 0.0f;

    const int NC = HH / BK;   // 16
    for (int c = 0; c < NC; c++) {
        if (c < NC - 1) { CP_WAIT(1); } else { CP_WAIT(0); }
        __syncthreads();
        if (c + 2 < NC) issue((c + 2) % NS);

        uint32_t sg = sb0 + (c % NS) * STG;
#pragma unroll
        for (int ko = 0; ko < 4; ko++) {
            unsigned af[4][4];
#pragma unroll
            for (int mt = 0; mt < 4; mt++)
                LDMX4(af[mt][0], af[mt][1], af[mt][2], af[mt][3], sg + aOff[mt] + ko * 32);
            unsigned bc[4], bn[4];
            LDMX4(bc[0], bc[1], bc[2], bc[3], sg + bOff[0] + ko * 32);
#pragma unroll
            for (int pr = 0; pr < 4; pr++) {
                if (pr < 3) LDMX4(bn[0], bn[1], bn[2], bn[3], sg + bOff[pr + 1] + ko * 32);
#pragma unroll
                for (int mt = 0; mt < 4; mt++) {
                    mmaf16(acc[mt][2 * pr],     af[mt], bc[0], bc[1]);
                    mmaf16(acc[mt][2 * pr + 1], af[mt], bc[2], bc[3]);
                }
#pragma unroll
                for (int q = 0; q < 4; q++) bc[q] = bn[q];
            }
        }
    }
    __syncthreads();

    // ---- epilogue: u-warps publish u; g-warps silu-combine in place; store f16 ----
    float* epf = (float*)dsm;   // 128 x 128, stride EPS
    if (half) {
#pragma unroll
        for (int mt = 0; mt < 4; mt++)
#pragma unroll
            for (int nt = 0; nt < 8; nt++)
#pragma unroll
                for (int i = 0; i < 4; i++) {
                    int row = wrow * 64 + mt * 16 + r4 + ((i >> 1) ? 8 : 0);
                    int col = wcol * 64 + nt * 8 + qk * 2 + (i & 1);
                    epf[row * EPS + col] = acc[mt][nt][i];
                }
    }
    __syncthreads();
    if (!half) {
#pragma unroll
        for (int mt = 0; mt < 4; mt++)
#pragma unroll
            for (int nt = 0; nt < 8; nt++)
#pragma unroll
                for (int i = 0; i < 4; i++) {
                    int row = wrow * 64 + mt * 16 + r4 + ((i >> 1) ? 8 : 0);
                    int col = wcol * 64 + nt * 8 + qk * 2 + (i & 1);
                    float u = epf[row * EPS + col];
                    float g = acc[mt][nt][i];
                    epf[row * EPS + col] = (g / (1.0f + expf(-g))) * u;
                }
    }
    __syncthreads();
    for (int idx = tid; idx < 128 * 128; idx += 256) {
        int rr = idx >> 7, cc = idx & 127;
        if (row0 + rr < n_e)
            g_act[(size_t)(base + row0 + rr) * FF + f0 + cc] = __float2half_rn(epf[rr * EPS + cc]);
    }
}

// ======================= GEMM2: y[slot] = wt * (act @ w2^T) =======================
// CTA: 128 slot-rows x 256 h-cols. B tile = 256 w2-rows. Same warp layout
// (half selects h-col block 0-127 / 128-255).
__global__ __launch_bounds__(256, 1)
void gemm2_kernel() {
    extern __shared__ char dsm[];
    __shared__ float s_wt[128];

    int ti = blockIdx.y;
    if (ti >= g_ntiles) return;
    int e    = g_tile_e[ti];
    int row0 = g_tile_row0[ti];
    int n_e  = g_counts[e];
    int h0   = blockIdx.x * 256;
    int base = g_offsets[e];
    int tid  = threadIdx.x;

    if (tid < 128) {
        int r = row0 + tid;
        s_wt[tid] = (r < n_e) ? g_pair_w[base + r] : 0.0f;
    }
    __syncthreads();

    const char* srcA[4];
    const char* srcB[8];
    int dofA[4], dofB[8];
#pragma unroll
    for (int i = 0; i < 4; i++) {
        int idx = tid + 256 * i;
        int row = idx >> 3, c = idx & 7;
        long arow = (long)base + row0 + row;
        if (arow > NPAIR - 1) arow = NPAIR - 1;
        srcA[i] = (const char*)(g_act + (size_t)arow * FF) + c * 16;
        dofA[i] = row * ROWB + c * 16;
    }
#pragma unroll
    for (int i = 0; i < 8; i++) {
        int idx = tid + 256 * i;
        int row = idx >> 3, c = idx & 7;
        srcB[i] = (const char*)(g_w2h + ((size_t)e * HH + h0 + row) * FF) + c * 16;
        dofB[i] = ASTG + row * ROWB + c * 16;
    }
    uint32_t sb0 = smem_u32(dsm);
    auto issue = [&](int s) {
        uint32_t sg = sb0 + s * STG;
#pragma unroll
        for (int i = 0; i < 4; i++) { CP16(sg + dofA[i], srcA[i]); srcA[i] += 128; }
#pragma unroll
        for (int i = 0; i < 8; i++) { CP16(sg + dofB[i], srcB[i]); srcB[i] += 128; }
        CP_COMMIT();
    };
    issue(0);
    issue(1);

    int wid = tid >> 5, lane = tid & 31;
    int half = wid >> 2;
    int wrow = wid & 1;
    int wcol = (wid >> 1) & 1;
    int r4 = lane >> 2, qk = lane & 3;
    int lane15 = lane & 15, laneHi = lane >> 4;
    int lane7 = lane & 7, half16 = (lane >> 3) & 1;

    uint32_t aOff[4];
#pragma unroll
    for (int mt = 0; mt < 4; mt++)
        aOff[mt] = (wrow * 64 + mt * 16 + lane15) * ROWB + laneHi * 16;
    uint32_t bOff[4];
#pragma unroll
    for (int pr = 0; pr < 4; pr++) {
        int ntsel = 2 * pr + (lane >> 4);
        bOff[pr] = ASTG + (half * 128 + wcol * 64 + ntsel * 8 + lane7) * ROWB + half16 * 16;
    }

    float acc[4][8][4];
#pragma unroll
    for (int mt = 0; mt < 4; mt++)
#pragma unroll
        for (int nt = 0; nt < 8; nt++)
#pragma unroll
            for (int i = 0; i < 4; i++) acc[mt][nt][i] = 0.0f;

    const int NC = FF / BK;   // 56
    for (int c = 0; c < NC; c++) {
        if (c < NC - 1) { CP_WAIT(1); } else { CP_WAIT(0); }
        __syncthreads();
        if (c + 2 < NC) issue((c + 2) % NS);

        uint32_t sg = sb0 + (c % NS) * STG;
#pragma unroll
        for (int ko = 0; ko < 4; ko++) {
            unsigned af[4][4];
#pragma unroll
            for (int mt = 0; mt < 4; mt++)
                LDMX4(af[mt][0], af[mt][1], af[mt][2], af[mt][3], sg + aOff[mt] + ko * 32);
            unsigned bc[4], bn[4];
            LDMX4(bc[0], bc[1], bc[2], bc[3], sg + bOff[0] + ko * 32);
#pragma unroll
            for (int pr = 0; pr < 4; pr++) {
                if (pr < 3) LDMX4(bn[0], bn[1], bn[2], bn[3], sg + bOff[pr + 1] + ko * 32);
#pragma unroll
                for (int mt = 0; mt < 4; mt++) {
                    mmaf16(acc[mt][2 * pr],     af[mt], bc[0], bc[1]);
                    mmaf16(acc[mt][2 * pr + 1], af[mt], bc[2], bc[3]);
                }
#pragma unroll
                for (int q = 0; q < 4; q++) bc[q] = bn[q];
            }
        }
    }

    // ---- epilogue: weighted non-atomic store to per-slot buffer ----
#pragma unroll
    for (int mt = 0; mt < 4; mt++)
#pragma unroll
        for (int i2 = 0; i2 < 2; i2++) {
            int row = wrow * 64 + mt * 16 + r4 + i2 * 8;
            if (row0 + row >= n_e) continue;
            float wt = s_wt[row];
            float* yp = g_y + (size_t)(base + row0 + row) * HH + h0 + half * 128 + wcol * 64;
#pragma unroll
            for (int nt = 0; nt < 8; nt++) {
                int col = nt * 8 + qk * 2;
                float2 v = make_float2(acc[mt][nt][i2 * 2] * wt, acc[mt][nt][i2 * 2 + 1] * wt);
                *(float2*)(yp + col) = v;
            }
        }
}

// ---------------- launch ----------------
extern "C" void kernel_launch(void* const* d_in, const int* in_sizes, int n_in,
                              void* d_out, int out_size) {
    (void)in_sizes; (void)n_in; (void)out_size;
    const float* x  = (const float*)d_in[0];
    const float* gw = (const float*)d_in[1];
    const float* w1 = (const float*)d_in[2];
    const float* w3 = (const float*)d_in[3];
    const float* w2 = (const float*)d_in[4];
    float* out = (float*)d_out;

    cudaFuncSetAttribute(gemm1_kernel, cudaFuncAttributeMaxDynamicSharedMemorySize, SMEM_DYN);
    cudaFuncSetAttribute(gemm2_kernel, cudaFuncAttributeMaxDynamicSharedMemorySize, SMEM_DYN);

    const int NCONV = 2 * N8_13 + N8_2;

    conv_x_kernel<<<(TT * HH + 255) / 256, 256>>>(x);
    conv_w_all_kernel<<<(NCONV + 255) / 256, 256>>>(w1, w3, w2);
    router_kernel<<<TT / 8, 256>>>(x, gw);
    build_kernel<<<1, 256>>>();

    dim3 g1(FF / 128, MAXTILES);   // (28, 40); inactive tiles early-exit
    gemm1_kernel<<<g1, 256, SMEM_DYN>>>();

    dim3 g2(HH / 256, MAXTILES);   // (4, 40)
    gemm2_kernel<<<g2, 256, SMEM_DYN>>>();

    combine_kernel<<<(TT * HH / 4 + 255) / 256, 256>>>(out);
}

// round 17
// speedup vs baseline: 1.1039x; 1.1039x over previous
#include <cuda_runtime.h>
#include <cuda_fp16.h>
#include <math.h>
#include <stdint.h>

// ---------------- problem constants ----------------
#define TT 2048
#define HH 1024
#define EE 8
#define FF 3584
#define TOPK 2
#define NPAIR (TT * TOPK)
#define BK 64               // K halfs per chunk (=128B per row)
#define NS 3                // pipeline stages
#define ROWB 144            // smem row stride bytes (128B data + 16B pad)
#define ASTG (128 * ROWB)   // 18432 B per operand tile
#define STG  (2 * ASTG)     // 36864 B per stage (A + B)
#define SMEM_DYN (NS * STG) // 110592 B ; x2 CTAs/SM = 221184
#define MAXTILES 40

// ---------------- device scratch (static; no allocation) ----------------
__device__ int    g_topk_idx[TT][TOPK];
__device__ float  g_topk_w[TT][TOPK];
__device__ int    g_counts[EE];
__device__ int    g_offsets[EE];
__device__ int    g_pair_token[NPAIR];
__device__ float  g_pair_w[NPAIR];
__device__ int    g_slot_of[NPAIR];
__device__ int    g_ntiles;
__device__ int    g_tile_e[MAXTILES];
__device__ int    g_tile_row0[MAXTILES];
__device__ __half g_xs[(size_t)TT * HH];
__device__ __half g_act[(size_t)NPAIR * FF];
__device__ __half g_w1h[(size_t)EE * FF * HH];
__device__ __half g_w3h[(size_t)EE * FF * HH];
__device__ __half g_w2h[(size_t)EE * HH * FF];
__device__ float  g_y[(size_t)NPAIR * HH];

// ---------------- helpers ----------------
__device__ __forceinline__ uint32_t smem_u32(const void* p) {
    uint32_t a;
    asm("{ .reg .u64 t; cvta.to.shared.u64 t, %1; cvt.u32.u64 %0, t; }" : "=r"(a) : "l"(p));
    return a;
}
#define CP16(dst_u32, src_ptr) \
    asm volatile("cp.async.cg.shared.global [%0], [%1], 16;" :: "r"(dst_u32), "l"(src_ptr) : "memory")
#define CP_COMMIT() asm volatile("cp.async.commit_group;" ::: "memory")
#define CP_WAIT(n)  asm volatile("cp.async.wait_group %0;" :: "n"(n) : "memory")
#define LDMX4(r0, r1, r2, r3, addr) \
    asm volatile("ldmatrix.sync.aligned.m8n8.x4.shared.b16 {%0,%1,%2,%3}, [%4];" \
                 : "=r"(r0), "=r"(r1), "=r"(r2), "=r"(r3) : "r"(addr))

__device__ __forceinline__ unsigned h2pack(float lo, float hi) {
    __half2 h = __floats2half2_rn(lo, hi);
    return *(unsigned*)&h;
}
__device__ __forceinline__ void mmaf16(float* c, const unsigned* a, unsigned b0, unsigned b1) {
    asm volatile(
        "mma.sync.aligned.m16n8k16.row.col.f32.f16.f16.f32 "
        "{%0,%1,%2,%3}, {%4,%5,%6,%7}, {%8,%9}, {%0,%1,%2,%3};"
        : "+f"(c[0]), "+f"(c[1]), "+f"(c[2]), "+f"(c[3])
        : "r"(a[0]), "r"(a[1]), "r"(a[2]), "r"(a[3]), "r"(b0), "r"(b1));
}

// ---------------- small kernels ----------------
__global__ void conv_x_kernel(const float* __restrict__ x) {
    int i = blockIdx.x * blockDim.x + threadIdx.x;
    if (i < TT * HH) g_xs[i] = __float2half_rn(x[i]);
}
__global__ void conv_w_kernel(const float* __restrict__ src, __half* __restrict__ dst, int n8) {
    int i = blockIdx.x * blockDim.x + threadIdx.x;
    if (i >= n8) return;
    const float4* s = (const float4*)src + 2 * (size_t)i;
    float4 a = s[0], b = s[1];
    uint4 o;
    o.x = h2pack(a.x, a.y);
    o.y = h2pack(a.z, a.w);
    o.z = h2pack(b.x, b.y);
    o.w = h2pack(b.z, b.w);
    ((uint4*)dst)[i] = o;
}
__global__ void router_kernel(const float* __restrict__ x, const float* __restrict__ gw) {
    int warp = (blockIdx.x * blockDim.x + threadIdx.x) >> 5;
    int lane = threadIdx.x & 31;
    if (warp >= TT) return;
    const float* xr = x + (size_t)warp * HH;
    float logit[EE];
#pragma unroll
    for (int e = 0; e < EE; e++) {
        const float* g = gw + (size_t)e * HH;
        float s = 0.0f;
        for (int i = lane; i < HH; i += 32) s += xr[i] * g[i];
#pragma unroll
        for (int o = 16; o > 0; o >>= 1) s += __shfl_xor_sync(0xffffffffu, s, o);
        logit[e] = s;
    }
    if (lane == 0) {
        int i0 = 0;
#pragma unroll
        for (int e = 1; e < EE; e++) if (logit[e] > logit[i0]) i0 = e;
        int i1 = (i0 == 0) ? 1 : 0;
#pragma unroll
        for (int e = 0; e < EE; e++) {
            if (e == i0) continue;
            if (logit[e] > logit[i1]) i1 = e;
        }
        float d = logit[i1] - logit[i0];
        float z = expf(d);
        float w0 = 1.0f / (1.0f + z);
        g_topk_idx[warp][0] = i0;
        g_topk_idx[warp][1] = i1;
        g_topk_w[warp][0] = w0;
        g_topk_w[warp][1] = z * w0;
    }
}
__global__ void build_kernel() {
    __shared__ int s_cnt[EE];
    __shared__ int s_cur[EE];
    int tid = threadIdx.x;
    if (tid < EE) s_cnt[tid] = 0;
    __syncthreads();
    for (int p = tid; p < NPAIR; p += blockDim.x)
        atomicAdd(&s_cnt[g_topk_idx[p >> 1][p & 1]], 1);
    __syncthreads();
    if (tid == 0) {
        int off = 0, nt = 0;
        for (int e = 0; e < EE; e++) {
            g_offsets[e] = off;
            g_counts[e]  = s_cnt[e];
            s_cur[e]     = off;
            for (int r0 = 0; r0 < s_cnt[e]; r0 += 128) {
                g_tile_e[nt]    = e;
                g_tile_row0[nt] = r0;
                nt++;
            }
            off += s_cnt[e];
        }
        g_ntiles = nt;
    }
    __syncthreads();
    for (int p = tid; p < NPAIR; p += blockDim.x) {
        int t = p >> 1, k = p & 1;
        int e = g_topk_idx[t][k];
        int slot = atomicAdd(&s_cur[e], 1);
        g_pair_token[slot] = t;
        g_pair_w[slot]     = g_topk_w[t][k];
        g_slot_of[p]       = slot;
    }
}
__global__ void combine_kernel(float* __restrict__ out) {
    int i = blockIdx.x * blockDim.x + threadIdx.x;
    if (i >= TT * HH / 4) return;
    int t = i >> 8;
    int c = (i & 255) << 2;
    int s0 = g_slot_of[2 * t];
    int s1 = g_slot_of[2 * t + 1];
    float4 a = *(const float4*)(g_y + (size_t)s0 * HH + c);
    float4 b = *(const float4*)(g_y + (size_t)s1 * HH + c);
    *(float4*)(out + (size_t)t * HH + c) =
        make_float4(a.x + b.x, a.y + b.y, a.z + b.z, a.w + b.w);
}

// ======================= GEMM1: act = silu(x@w1^T) * (x@w3^T) =======================
__global__ __launch_bounds__(256, 2)
void gemm1_kernel() {
    extern __shared__ char dsm[];
    __shared__ int s_tok[128];

    int ti = blockIdx.y;
    if (ti >= g_ntiles) return;
    int e    = g_tile_e[ti];
    int row0 = g_tile_row0[ti];
    int n_e  = g_counts[e];
    int f0   = blockIdx.x * 64;
    int base = g_offsets[e];
    int tid  = threadIdx.x;

    if (tid < 128) {
        int r = row0 + tid;
        s_tok[tid] = (r < n_e) ? g_pair_token[base + r] : 0;
    }
    __syncthreads();

    const char* srcA[4];
    const char* srcB[4];
    int dofA[4], dofB[4];
#pragma unroll
    for (int i = 0; i < 4; i++) {
        int idx = tid + 256 * i;
        int row = idx >> 3, c = idx & 7;
        srcA[i] = (const char*)(g_xs + (size_t)s_tok[row] * HH) + c * 16;
        const __half* wb = (row < 64)
            ? g_w1h + ((size_t)e * FF + f0 + row) * HH
            : g_w3h + ((size_t)e * FF + f0 + row - 64) * HH;
        srcB[i] = (const char*)wb + c * 16;
        dofA[i] = row * ROWB + c * 16;
        dofB[i] = ASTG + row * ROWB + c * 16;
    }
    uint32_t sb0 = smem_u32(dsm);
    auto issue = [&](int s) {
        uint32_t sg = sb0 + s * STG;
#pragma unroll
        for (int i = 0; i < 4; i++) { CP16(sg + dofA[i], srcA[i]); srcA[i] += 128; }
#pragma unroll
        for (int i = 0; i < 4; i++) { CP16(sg + dofB[i], srcB[i]); srcB[i] += 128; }
        CP_COMMIT();
    };
    issue(0);
    issue(1);

    int wid = tid >> 5, lane = tid & 31;
    int isU = wid >> 2;
    int rowblk = (wid & 3) * 32;
    int r4 = lane >> 2, qk = lane & 3;
    int lane15 = lane & 15, laneHi = lane >> 4;
    int lane7 = lane & 7, half16 = (lane >> 3) & 1;

    uint32_t aOff[2];
#pragma unroll
    for (int mt = 0; mt < 2; mt++)
        aOff[mt] = (rowblk + mt * 16 + lane15) * ROWB + laneHi * 16;
    uint32_t bOff[4];
#pragma unroll
    for (int pr = 0; pr < 4; pr++) {
        int ntsel = 2 * pr + (lane >> 4);
        bOff[pr] = ASTG + (isU * 64 + ntsel * 8 + lane7) * ROWB + half16 * 16;
    }

    float acc[2][8][4];
#pragma unroll
    for (int mt = 0; mt < 2; mt++)
#pragma unroll
        for (int nt = 0; nt < 8; nt++)
#pragma unroll
            for (int i = 0; i < 4; i++) acc[mt][nt][i] = 0.0f;

    const int NC = HH / BK;   // 16
    for (int c = 0; c < NC; c++) {
        if (c < NC - 1) { CP_WAIT(1); } else { CP_WAIT(0); }
        __syncthreads();
        if (c + 2 < NC) issue((c + 2) % NS);

        uint32_t sg = sb0 + (c % NS) * STG;
#pragma unroll
        for (int ko = 0; ko < 4; ko++) {
            unsigned af[2][4];
            LDMX4(af[0][0], af[0][1], af[0][2], af[0][3], sg + aOff[0] + ko * 32);
            LDMX4(af[1][0], af[1][1], af[1][2], af[1][3], sg + aOff[1] + ko * 32);
            unsigned bc[4], bn[4];
            LDMX4(bc[0], bc[1], bc[2], bc[3], sg + bOff[0] + ko * 32);
#pragma unroll
            for (int pr = 0; pr < 4; pr++) {
                if (pr < 3) LDMX4(bn[0], bn[1], bn[2], bn[3], sg + bOff[pr + 1] + ko * 32);
                mmaf16(acc[0][2 * pr],     af[0], bc[0], bc[1]);
                mmaf16(acc[1][2 * pr],     af[1], bc[0], bc[1]);
                mmaf16(acc[0][2 * pr + 1], af[0], bc[2], bc[3]);
                mmaf16(acc[1][2 * pr + 1], af[1], bc[2], bc[3]);
#pragma unroll
                for (int q = 0; q < 4; q++) bc[q] = bn[q];
            }
        }
    }
    __syncthreads();

    // ---- epilogue ----
    float* epf = (float*)dsm;
    if (isU) {
#pragma unroll
        for (int mt = 0; mt < 2; mt++)
#pragma unroll
            for (int nt = 0; nt < 8; nt++)
#pragma unroll
                for (int i = 0; i < 4; i++) {
                    int row = rowblk + mt * 16 + r4 + ((i >> 1) ? 8 : 0);
                    int col = nt * 8 + qk * 2 + (i & 1);
                    epf[row * 66 + col] = acc[mt][nt][i];
                }
    }
    __syncthreads();
    if (!isU) {
#pragma unroll
        for (int mt = 0; mt < 2; mt++)
#pragma unroll
            for (int nt = 0; nt < 8; nt++)
#pragma unroll
                for (int i = 0; i < 4; i++) {
                    int row = rowblk + mt * 16 + r4 + ((i >> 1) ? 8 : 0);
                    int col = nt * 8 + qk * 2 + (i & 1);
                    float u = epf[row * 66 + col];
                    float g = acc[mt][nt][i];
                    epf[row * 66 + col] = (g / (1.0f + expf(-g))) * u;
                }
    }
    __syncthreads();
    for (int idx = tid; idx < 128 * 64; idx += 256) {
        int rr = idx >> 6, cc = idx & 63;
        if (row0 + rr < n_e)
            g_act[(size_t)(base + row0 + rr) * FF + f0 + cc] = __float2half_rn(epf[rr * 66 + cc]);
    }
}

// ======================= GEMM2: y[slot] = wt * (act @ w2^T) =======================
__global__ __launch_bounds__(256, 2)
void gemm2_kernel() {
    extern __shared__ char dsm[];
    __shared__ float s_wt[128];

    int ti = blockIdx.y;
    if (ti >= g_ntiles) return;
    int e    = g_tile_e[ti];
    int row0 = g_tile_row0[ti];
    int n_e  = g_counts[e];
    int h0   = blockIdx.x * 128;
    int base = g_offsets[e];
    int tid  = threadIdx.x;

    if (tid < 128) {
        int r = row0 + tid;
        s_wt[tid] = (r < n_e) ? g_pair_w[base + r] : 0.0f;
    }
    __syncthreads();

    const char* srcA[4];
    const char* srcB[4];
    int dofA[4], dofB[4];
#pragma unroll
    for (int i = 0; i < 4; i++) {
        int idx = tid + 256 * i;
        int row = idx >> 3, c = idx & 7;
        long arow = (long)base + row0 + row;
        if (arow > NPAIR - 1) arow = NPAIR - 1;
        srcA[i] = (const char*)(g_act + (size_t)arow * FF) + c * 16;
        srcB[i] = (const char*)(g_w2h + ((size_t)e * HH + h0 + row) * FF) + c * 16;
        dofA[i] = row * ROWB + c * 16;
        dofB[i] = ASTG + row * ROWB + c * 16;
    }
    uint32_t sb0 = smem_u32(dsm);
    auto issue = [&](int s) {
        uint32_t sg = sb0 + s * STG;
#pragma unroll
        for (int i = 0; i < 4; i++) { CP16(sg + dofA[i], srcA[i]); srcA[i] += 128; }
#pragma unroll
        for (int i = 0; i < 4; i++) { CP16(sg + dofB[i], srcB[i]); srcB[i] += 128; }
        CP_COMMIT();
    };
    issue(0);
    issue(1);

    int wid = tid >> 5, lane = tid & 31;
    int rowblk = (wid & 3) * 32;
    int colblk = (wid >> 2) * 64;
    int r4 = lane >> 2, qk = lane & 3;
    int lane15 = lane & 15, laneHi = lane >> 4;
    int lane7 = lane & 7, half16 = (lane >> 3) & 1;

    uint32_t aOff[2];
#pragma unroll
    for (int mt = 0; mt < 2; mt++)
        aOff[mt] = (rowblk + mt * 16 + lane15) * ROWB + laneHi * 16;
    uint32_t bOff[4];
#pragma unroll
    for (int pr = 0; pr < 4; pr++) {
        int ntsel = 2 * pr + (lane >> 4);
        bOff[pr] = ASTG + (colblk + ntsel * 8 + lane7) * ROWB + half16 * 16;
    }

    float acc[2][8][4];
#pragma unroll
    for (int mt = 0; mt < 2; mt++)
#pragma unroll
        for (int nt = 0; nt < 8; nt++)
#pragma unroll
            for (int i = 0; i < 4; i++) acc[mt][nt][i] = 0.0f;

    const int NC = FF / BK;   // 56
    for (int c = 0; c < NC; c++) {
        if (c < NC - 1) { CP_WAIT(1); } else { CP_WAIT(0); }
        __syncthreads();
        if (c + 2 < NC) issue((c + 2) % NS);

        uint32_t sg = sb0 + (c % NS) * STG;
#pragma unroll
        for (int ko = 0; ko < 4; ko++) {
            unsigned af[2][4];
            LDMX4(af[0][0], af[0][1], af[0][2], af[0][3], sg + aOff[0] + ko * 32);
            LDMX4(af[1][0], af[1][1], af[1][2], af[1][3], sg + aOff[1] + ko * 32);
            unsigned bc[4], bn[4];
            LDMX4(bc[0], bc[1], bc[2], bc[3], sg + bOff[0] + ko * 32);
#pragma unroll
            for (int pr = 0; pr < 4; pr++) {
                if (pr < 3) LDMX4(bn[0], bn[1], bn[2], bn[3], sg + bOff[pr + 1] + ko * 32);
                mmaf16(acc[0][2 * pr],     af[0], bc[0], bc[1]);
                mmaf16(acc[1][2 * pr],     af[1], bc[0], bc[1]);
                mmaf16(acc[0][2 * pr + 1], af[0], bc[2], bc[3]);
                mmaf16(acc[1][2 * pr + 1], af[1], bc[2], bc[3]);
#pragma unroll
                for (int q = 0; q < 4; q++) bc[q] = bn[q];
            }
        }
    }

    // ---- epilogue: weighted non-atomic store to per-slot buffer ----
#pragma unroll
    for (int mt = 0; mt < 2; mt++)
#pragma unroll
        for (int i2 = 0; i2 < 2; i2++) {
            int row = rowblk + mt * 16 + r4 + i2 * 8;
            if (row0 + row >= n_e) continue;
            float wt = s_wt[row];
            float* yp = g_y + (size_t)(base + row0 + row) * HH + h0;
#pragma unroll
            for (int nt = 0; nt < 8; nt++) {
                int col = colblk + nt * 8 + qk * 2;
                float2 v = make_float2(acc[mt][nt][i2 * 2] * wt, acc[mt][nt][i2 * 2 + 1] * wt);
                *(float2*)(yp + col) = v;
            }
        }
}

// ---------------- launch ----------------
extern "C" void kernel_launch(void* const* d_in, const int* in_sizes, int n_in,
                              void* d_out, int out_size) {
    (void)in_sizes; (void)n_in; (void)out_size;
    const float* x  = (const float*)d_in[0];
    const float* gw = (const float*)d_in[1];
    const float* w1 = (const float*)d_in[2];
    const float* w3 = (const float*)d_in[3];
    const float* w2 = (const float*)d_in[4];
    float* out = (float*)d_out;

    // one-time resources (no device memory involved)
    static bool inited = false;
    static cudaStream_t s2, s3;
    static cudaEvent_t ev0, ev2, ev3;
    static __half *w1h_p, *w3h_p, *w2h_p;
    if (!inited) {
        cudaStreamCreateWithFlags(&s2, cudaStreamNonBlocking);
        cudaStreamCreateWithFlags(&s3, cudaStreamNonBlocking);
        cudaEventCreateWithFlags(&ev0, cudaEventDisableTiming);
        cudaEventCreateWithFlags(&ev2, cudaEventDisableTiming);
        cudaEventCreateWithFlags(&ev3, cudaEventDisableTiming);
        cudaGetSymbolAddress((void**)&w1h_p, g_w1h);
        cudaGetSymbolAddress((void**)&w3h_p, g_w3h);
        cudaGetSymbolAddress((void**)&w2h_p, g_w2h);
        cudaFuncSetAttribute(gemm1_kernel, cudaFuncAttributeMaxDynamicSharedMemorySize, SMEM_DYN);
        cudaFuncSetAttribute(gemm2_kernel, cudaFuncAttributeMaxDynamicSharedMemorySize, SMEM_DYN);
        inited = true;
    }

    const int N8_13 = EE * FF * HH / 8;
    const int N8_2  = EE * HH * FF / 8;

    // fork: s2 <- gemm1-side conversions, s3 <- w2 conversion
    cudaEventRecord(ev0, 0);
    cudaStreamWaitEvent(s2, ev0, 0);
    cudaStreamWaitEvent(s3, ev0, 0);

    conv_x_kernel<<<(TT * HH + 255) / 256, 256, 0, s2>>>(x);
    conv_w_kernel<<<(N8_13 + 255) / 256, 256, 0, s2>>>(w1, w1h_p, N8_13);
    conv_w_kernel<<<(N8_13 + 255) / 256, 256, 0, s2>>>(w3, w3h_p, N8_13);
    conv_w_kernel<<<(N8_2  + 255) / 256, 256, 0, s3>>>(w2, w2h_p, N8_2);

    router_kernel<<<TT / 8, 256>>>(x, gw);    // main stream
    build_kernel<<<1, 256>>>();

    // join s2 before gemm1
    cudaEventRecord(ev2, s2);
    cudaStreamWaitEvent(0, ev2, 0);

    dim3 g1(FF / 64, MAXTILES);
    gemm1_kernel<<<g1, 256, SMEM_DYN>>>();

    // join s3 before gemm2 (w2 conversion hidden under gemm1)
    cudaEventRecord(ev3, s3);
    cudaStreamWaitEvent(0, ev3, 0);

    dim3 g2(HH / 128, MAXTILES);
    gemm2_kernel<<<g2, 256, SMEM_DYN>>>();

    combine_kernel<<<(TT * HH / 4 + 255) / 256, 256>>>(out);
}